// round 1
// baseline (speedup 1.0000x reference)
#include <cuda_runtime.h>

#define NN   10000
#define FIN  512
#define ED   256
#define H0D  512
#define H1D  256
#define NE   160000
#define TT   (NE + NN)
#define TPAD ((TT + 63) & ~63)

// Scratch (device globals: no allocation allowed)
__device__ float g_A[NN * H0D];                     // emb @ W0[:256,:] + b0
__device__ float g_B[NN * H0D];                     // emb @ W0[256:,:]
__device__ float g_h[(size_t)TPAD * H1D];           // layer-2 activations per entry
__device__ unsigned long long g_seg[NN];            // per-node (lk_bits<<32 | idx) argmax
__device__ int g_owner[NN];                         // per-target winning source node

__device__ __forceinline__ unsigned int fenc(float f) {
    unsigned int u = __float_as_uint(f);
    return (u & 0x80000000u) ? ~u : (u | 0x80000000u);  // monotone float->uint
}

__global__ void k_init() {
    int i = blockIdx.x * blockDim.x + threadIdx.x;
    if (i < NN) { g_seg[i] = 0ull; g_owner[i] = -1; }
}

// ---------------------------------------------------------------------------
// Generic fp32 GEMM: C[64 rows x 256 cols per block] = relu?(A[M,K] @ B[K,*] + bias)
// csel: 0 -> Cp, 1 -> g_A, 2 -> g_B
// ---------------------------------------------------------------------------
__global__ __launch_bounds__(256) void k_gemm(
    const float* __restrict__ A, int M, int K, int lda,
    const float* __restrict__ B, int ldb,
    const float* __restrict__ bias,
    float* __restrict__ Cp, int csel, int ldc, int do_relu)
{
    __shared__ float As[32][68];
    __shared__ float Bs[32 * 256];
    float* C = (csel == 1) ? g_A : (csel == 2) ? g_B : Cp;

    const int row0  = blockIdx.x * 64;
    const int gcol0 = blockIdx.y * 256;
    const int tid = threadIdx.x;
    const int cg = tid & 31, eg = tid >> 5;

    float acc[8][8];
    #pragma unroll
    for (int i = 0; i < 8; i++)
        #pragma unroll
        for (int j = 0; j < 8; j++) acc[i][j] = 0.f;

    for (int k0 = 0; k0 < K; k0 += 32) {
        #pragma unroll
        for (int l = 0; l < 8; l++) {
            int idx = tid + l * 256;
            int r = idx >> 5, kk = idx & 31;
            int gr = row0 + r;
            As[kk][r] = (gr < M) ? A[(size_t)gr * lda + k0 + kk] : 0.f;
        }
        #pragma unroll
        for (int l = 0; l < 8; l++) {
            int idx4 = tid + l * 256;           // float4 index
            int kk = idx4 >> 6, c = (idx4 << 2) & 255;
            *(float4*)&Bs[kk * 256 + c] =
                *(const float4*)&B[(size_t)(k0 + kk) * ldb + gcol0 + c];
        }
        __syncthreads();
        #pragma unroll
        for (int kk = 0; kk < 32; kk++) {
            float a[8], b[8];
            *(float4*)(a)     = *(const float4*)&As[kk][eg * 8];
            *(float4*)(a + 4) = *(const float4*)&As[kk][eg * 8 + 4];
            *(float4*)(b)     = *(const float4*)&Bs[kk * 256 + cg * 8];
            *(float4*)(b + 4) = *(const float4*)&Bs[kk * 256 + cg * 8 + 4];
            #pragma unroll
            for (int i = 0; i < 8; i++)
                #pragma unroll
                for (int j = 0; j < 8; j++)
                    acc[i][j] = fmaf(a[i], b[j], acc[i][j]);
        }
        __syncthreads();
    }

    float bb[8];
    #pragma unroll
    for (int j = 0; j < 8; j++) bb[j] = bias ? bias[gcol0 + cg * 8 + j] : 0.f;

    #pragma unroll
    for (int i = 0; i < 8; i++) {
        int gr = row0 + eg * 8 + i;
        if (gr >= M) continue;
        float out[8];
        #pragma unroll
        for (int j = 0; j < 8; j++) {
            float v = acc[i][j] + bb[j];
            out[j] = do_relu ? fmaxf(v, 0.f) : v;
        }
        *(float4*)&C[(size_t)gr * ldc + gcol0 + cg * 8]     = *(float4*)out;
        *(float4*)&C[(size_t)gr * ldc + gcol0 + cg * 8 + 4] = *(float4*)(out + 4);
    }
}

// ---------------------------------------------------------------------------
// MLP2: per entry t: h1 = relu(A[seg] + B[dst]), h = relu(h1@W1 + b1),
//       lk = h . Wlk + blk ; store h, atomic segmax of (lk, t).
// 64 entries/block, K=512 chunked by 32.
// ---------------------------------------------------------------------------
__global__ __launch_bounds__(256) void k_mlp2(
    const float* __restrict__ W1, const float* __restrict__ b1,
    const float* __restrict__ Wlk, const float* __restrict__ blk,
    const int* __restrict__ esrc, const int* __restrict__ edst)
{
    __shared__ float Zs[32][68];
    __shared__ float Bs[32 * 256];
    __shared__ int s_src[64], s_dst[64];

    const int t0 = blockIdx.x * 64;
    const int tid = threadIdx.x;
    const int cg = tid & 31, eg = tid >> 5;

    if (tid < 64) {
        int t = t0 + tid;
        int s = -1, d = -1;
        if (t < TT) {
            if (t < NE) { s = esrc[t]; d = edst[t]; }
            else        { s = t - NE; }
        }
        s_src[tid] = s; s_dst[tid] = d;
    }
    __syncthreads();

    float acc[8][8];
    #pragma unroll
    for (int i = 0; i < 8; i++)
        #pragma unroll
        for (int j = 0; j < 8; j++) acc[i][j] = 0.f;

    for (int k0 = 0; k0 < H0D; k0 += 32) {
        #pragma unroll
        for (int l = 0; l < 8; l++) {
            int idx = tid + l * 256;
            int e = idx >> 5, kk = idx & 31;
            int s = s_src[e];
            float v = 0.f;
            if (s >= 0) {
                v = g_A[(size_t)s * H0D + k0 + kk];
                int d = s_dst[e];
                if (d >= 0) v += g_B[(size_t)d * H0D + k0 + kk];
                v = fmaxf(v, 0.f);
            }
            Zs[kk][e] = v;
        }
        #pragma unroll
        for (int l = 0; l < 8; l++) {
            int idx4 = tid + l * 256;
            int kk = idx4 >> 6, c = (idx4 << 2) & 255;
            *(float4*)&Bs[kk * 256 + c] =
                *(const float4*)&W1[(size_t)(k0 + kk) * H1D + c];
        }
        __syncthreads();
        #pragma unroll
        for (int kk = 0; kk < 32; kk++) {
            float a[8], b[8];
            *(float4*)(a)     = *(const float4*)&Zs[kk][eg * 8];
            *(float4*)(a + 4) = *(const float4*)&Zs[kk][eg * 8 + 4];
            *(float4*)(b)     = *(const float4*)&Bs[kk * 256 + cg * 8];
            *(float4*)(b + 4) = *(const float4*)&Bs[kk * 256 + cg * 8 + 4];
            #pragma unroll
            for (int i = 0; i < 8; i++)
                #pragma unroll
                for (int j = 0; j < 8; j++)
                    acc[i][j] = fmaf(a[i], b[j], acc[i][j]);
        }
        __syncthreads();
    }

    float bb[8], wl[8];
    #pragma unroll
    for (int j = 0; j < 8; j++) {
        bb[j] = b1[cg * 8 + j];
        wl[j] = Wlk[cg * 8 + j];
    }

    float lkp[8];
    #pragma unroll
    for (int i = 0; i < 8; i++) {
        int t = t0 + eg * 8 + i;
        float h[8];
        float p = 0.f;
        #pragma unroll
        for (int j = 0; j < 8; j++) {
            h[j] = fmaxf(acc[i][j] + bb[j], 0.f);
            p = fmaf(h[j], wl[j], p);
        }
        *(float4*)&g_h[(size_t)t * H1D + cg * 8]     = *(float4*)h;
        *(float4*)&g_h[(size_t)t * H1D + cg * 8 + 4] = *(float4*)(h + 4);
        #pragma unroll
        for (int off = 16; off; off >>= 1)
            p += __shfl_xor_sync(0xffffffffu, p, off);
        lkp[i] = p;
    }

    if (cg == 0) {
        float lb = blk[0];
        #pragma unroll
        for (int i = 0; i < 8; i++) {
            int t = t0 + eg * 8 + i;
            if (t < TT) {
                float lk = lkp[i] + lb;
                unsigned long long key =
                    ((unsigned long long)fenc(lk) << 32) | (unsigned int)t;
                atomicMax(&g_seg[s_src[eg * 8 + i]], key);
            }
        }
    }
}

// ---------------------------------------------------------------------------
// Per node: decode winner, action head, register update target (last-i-wins).
// One warp per node.
// ---------------------------------------------------------------------------
__global__ void k_final(const float* __restrict__ Wa, const float* __restrict__ ba,
                        const int* __restrict__ edst)
{
    int warp = (blockIdx.x * blockDim.x + threadIdx.x) >> 5;
    int lane = threadIdx.x & 31;
    if (warp >= NN) return;
    unsigned long long key = g_seg[warp];
    int win = (int)(unsigned int)(key & 0xffffffffull);
    int chosen = (win < NE) ? edst[win] : -1;

    const float* h = &g_h[(size_t)win * H1D];
    float s0 = 0.f, s1 = 0.f;
    #pragma unroll
    for (int j = 0; j < 8; j++) {
        float hv = h[lane + j * 32];
        s0 = fmaf(hv, Wa[(lane + j * 32) * 2 + 0], s0);
        s1 = fmaf(hv, Wa[(lane + j * 32) * 2 + 1], s1);
    }
    #pragma unroll
    for (int off = 16; off; off >>= 1) {
        s0 += __shfl_xor_sync(0xffffffffu, s0, off);
        s1 += __shfl_xor_sync(0xffffffffu, s1, off);
    }
    if (lane == 0) {
        float l0 = s0 + ba[0], l1 = s1 + ba[1];
        if (chosen >= 0 && (l1 > l0))   // at==1 iff strictly greater (argmax tie -> 0)
            atomicMax(&g_owner[chosen], warp);
    }
}

// ---------------------------------------------------------------------------
// Recompute updated rows: out[t] = relu(0.5*(feature[i]+feature[t]) @ We + be)
// One block per target; inactive targets exit.
// ---------------------------------------------------------------------------
__global__ __launch_bounds__(256) void k_newval(
    const float* __restrict__ feature, const float* __restrict__ We,
    const float* __restrict__ be, float* __restrict__ out)
{
    int t = blockIdx.x;
    int i = g_owner[t];
    if (i < 0) return;
    __shared__ float mf[FIN];
    int tid = threadIdx.x;
    for (int k = tid; k < FIN; k += 256)
        mf[k] = 0.5f * (feature[(size_t)i * FIN + k] + feature[(size_t)t * FIN + k]);
    __syncthreads();
    float acc = 0.f;
    #pragma unroll 8
    for (int k = 0; k < FIN; k++)
        acc = fmaf(mf[k], We[(size_t)k * ED + tid], acc);
    out[(size_t)t * ED + tid] = fmaxf(acc + be[tid], 0.f);
}

// ---------------------------------------------------------------------------
extern "C" void kernel_launch(void* const* d_in, const int* in_sizes, int n_in,
                              void* d_out, int out_size) {
    const float* feature = (const float*)d_in[0];
    const float* We      = (const float*)d_in[1];
    const float* be      = (const float*)d_in[2];
    const float* W0      = (const float*)d_in[3];
    const float* b0      = (const float*)d_in[4];
    const float* W1      = (const float*)d_in[5];
    const float* b1      = (const float*)d_in[6];
    const float* Wlk     = (const float*)d_in[7];
    const float* blk     = (const float*)d_in[8];
    const float* Wa      = (const float*)d_in[9];
    const float* ba      = (const float*)d_in[10];
    const int*   esrc    = (const int*)d_in[11];
    const int*   edst    = (const int*)d_in[12];
    float* out = (float*)d_out;

    k_init<<<(NN + 255) / 256, 256>>>();

    // emb = relu(feature @ We + be) -> out (output starts as emb)
    k_gemm<<<dim3((NN + 63) / 64, 1), 256>>>(feature, NN, FIN, FIN,
                                             We, ED, be, out, 0, ED, 1);
    // g_A = emb @ W0[0:256,:] + b0   (bias folded here once)
    k_gemm<<<dim3((NN + 63) / 64, 2), 256>>>(out, NN, ED, ED,
                                             W0, H0D, b0, nullptr, 1, H0D, 0);
    // g_B = emb @ W0[256:512,:]
    k_gemm<<<dim3((NN + 63) / 64, 2), 256>>>(out, NN, ED, ED,
                                             W0 + 256 * H0D, H0D, nullptr,
                                             nullptr, 2, H0D, 0);

    k_mlp2<<<(TT + 63) / 64, 256>>>(W1, b1, Wlk, blk, esrc, edst);
    k_final<<<(NN * 32 + 255) / 256, 256>>>(Wa, ba, edst);
    k_newval<<<NN, 256>>>(feature, We, be, out);
}